// round 2
// baseline (speedup 1.0000x reference)
#include <cuda_runtime.h>

#define N_NODES 40000
#define D_IN    512
#define D_OUT   128
#define N_EDGES 640000

// Scratch for seq = X @ W^T  (40000 x 128 fp32 = 20.5 MB) — device global, no alloc.
__device__ float g_seq[N_NODES * D_OUT];

// ---------------------------------------------------------------------------
// Kernel 1: seq[n][o] = sum_k x[n][k] * w[o][k]
// Classic smem-tiled FFMA GEMM. BM=64, BN=128, BK=16, 256 threads,
// each thread computes an 8x4 micro-tile.
// ---------------------------------------------------------------------------
#define BM 64
#define BN 128
#define BK 16
#define TM 8
#define TN 4

__global__ __launch_bounds__(256) void gemm_kernel(const float* __restrict__ x,
                                                   const float* __restrict__ w)
{
    __shared__ float As[BK][BM + 4];   // [k][row], padded vs bank conflicts
    __shared__ float Ws[BK][BN + 4];   // [k][col]

    const int tid = threadIdx.x;
    const int tx  = tid & 31;   // column group: cols tx*4 .. tx*4+3
    const int ty  = tid >> 5;   // row group:    rows ty*8 .. ty*8+7
    const int blockRow = blockIdx.x * BM;

    float acc[TM][TN];
    #pragma unroll
    for (int i = 0; i < TM; i++)
        #pragma unroll
        for (int j = 0; j < TN; j++) acc[i][j] = 0.f;

    for (int kt = 0; kt < D_IN; kt += BK) {
        // A tile: 64 rows x 16 k  (1024 elems, 4 per thread)
        #pragma unroll
        for (int i = 0; i < (BM * BK) / 256; i++) {
            int e = i * 256 + tid;
            int r = e >> 4;
            int k = e & 15;
            As[k][r] = x[(blockRow + r) * D_IN + kt + k];
        }
        // W tile: 128 cols x 16 k (2048 elems, 8 per thread)
        #pragma unroll
        for (int i = 0; i < (BN * BK) / 256; i++) {
            int e = i * 256 + tid;
            int c = e >> 4;
            int k = e & 15;
            Ws[k][c] = w[c * D_IN + kt + k];
        }
        __syncthreads();

        #pragma unroll
        for (int kk = 0; kk < BK; kk++) {
            float a[TM], b[TN];
            #pragma unroll
            for (int i = 0; i < TM; i++) a[i] = As[kk][ty * TM + i];
            #pragma unroll
            for (int j = 0; j < TN; j++) b[j] = Ws[kk][tx * TN + j];
            #pragma unroll
            for (int i = 0; i < TM; i++)
                #pragma unroll
                for (int j = 0; j < TN; j++)
                    acc[i][j] = fmaf(a[i], b[j], acc[i][j]);
        }
        __syncthreads();
    }

    #pragma unroll
    for (int i = 0; i < TM; i++) {
        int row = blockRow + ty * TM + i;
        float4 v = make_float4(acc[i][0], acc[i][1], acc[i][2], acc[i][3]);
        *reinterpret_cast<float4*>(&g_seq[row * D_OUT + tx * TN]) = v;
    }
}

// ---------------------------------------------------------------------------
// Kernel 2: out[n][o] = bias[o]   (out is poisoned before timing)
// ---------------------------------------------------------------------------
__global__ void init_kernel(float* __restrict__ out, const float* __restrict__ bias)
{
    int i = blockIdx.x * blockDim.x + threadIdx.x;
    if (i < N_NODES * D_OUT) out[i] = bias[i & (D_OUT - 1)];
}

// ---------------------------------------------------------------------------
// Kernel 3: scatter-add.  One warp per edge; lane j handles 4 consecutive
// output features via float4 load of seq[col] + 4 atomicAdds into out[row].
// seq (20.5 MB) and out (20.5 MB) both live in L2.
// ---------------------------------------------------------------------------
__global__ __launch_bounds__(256) void scatter_kernel(const float* __restrict__ ev,
                                                      const int*   __restrict__ er,
                                                      const int*   __restrict__ ec,
                                                      float*       __restrict__ out)
{
    long long idx = (long long)blockIdx.x * blockDim.x + threadIdx.x;
    int e    = (int)(idx >> 5);
    int lane = (int)(idx & 31);
    if (e >= N_EDGES) return;

    int   row = er[e];
    int   col = ec[e];
    float v   = ev[e];

    const float4 s = reinterpret_cast<const float4*>(g_seq)[col * 32 + lane];
    float* o = out + (long long)row * D_OUT + lane * 4;
    atomicAdd(o + 0, v * s.x);
    atomicAdd(o + 1, v * s.y);
    atomicAdd(o + 2, v * s.z);
    atomicAdd(o + 3, v * s.w);
}

// ---------------------------------------------------------------------------
// Kernel 4: PReLU in place (single shared slope alpha[0]).
// ---------------------------------------------------------------------------
__global__ void prelu_kernel(float* __restrict__ out, const float* __restrict__ alpha)
{
    int i = blockIdx.x * blockDim.x + threadIdx.x;
    if (i >= (N_NODES * D_OUT) / 4) return;
    float a = alpha[0];
    float4 v = reinterpret_cast<float4*>(out)[i];
    v.x = v.x > 0.f ? v.x : a * v.x;
    v.y = v.y > 0.f ? v.y : a * v.y;
    v.z = v.z > 0.f ? v.z : a * v.z;
    v.w = v.w > 0.f ? v.w : a * v.w;
    reinterpret_cast<float4*>(out)[i] = v;
}

// ---------------------------------------------------------------------------
// Launch. Input order (metadata): x, weight, bias, alpha, edge_val, edge_row,
// edge_col. Output: fp32 [40000*128].
// ---------------------------------------------------------------------------
extern "C" void kernel_launch(void* const* d_in, const int* in_sizes, int n_in,
                              void* d_out, int out_size)
{
    const float* x     = (const float*)d_in[0];
    const float* w     = (const float*)d_in[1];
    const float* bias  = (const float*)d_in[2];
    const float* alpha = (const float*)d_in[3];
    const float* ev    = (const float*)d_in[4];
    const int*   er    = (const int*)  d_in[5];
    const int*   ec    = (const int*)  d_in[6];
    float*       out   = (float*)d_out;

    // 1) GEMM: 40000/64 = 625 blocks
    gemm_kernel<<<N_NODES / BM, 256>>>(x, w);

    // 2) out = bias
    {
        int n = N_NODES * D_OUT;
        init_kernel<<<(n + 255) / 256, 256>>>(out, bias);
    }

    // 3) scatter-add: 640000 edges * 32 lanes = 20.48M threads
    {
        long long threads = (long long)N_EDGES * 32;
        int blocks = (int)((threads + 255) / 256);
        scatter_kernel<<<blocks, 256>>>(ev, er, ec, out);
    }

    // 4) PReLU
    {
        int n4 = (N_NODES * D_OUT) / 4;
        prelu_kernel<<<(n4 + 255) / 256, 256>>>(out, alpha);
    }
}

// round 4
// speedup vs baseline: 1.1424x; 1.1424x over previous
#include <cuda_runtime.h>

#define N_NODES 40000
#define D_IN    512
#define D_OUT   128
#define N_EDGES 640000

// Scratch for seq = X @ W^T  (40000 x 128 fp32 = 20.5 MB) — device global, no alloc.
__device__ float g_seq[N_NODES * D_OUT];

// ---------------------------------------------------------------------------
// Kernel 1: seq[n][o] = sum_k x[n][k] * w[o][k]
// smem-tiled FFMA GEMM. BM=128, BN=128, BK=16, 256 threads, 8x8 micro-tile.
// ---------------------------------------------------------------------------
#define BM 128
#define BN 128
#define BK 16
#define TM 8
#define TN 8

__global__ __launch_bounds__(256) void gemm_kernel(const float* __restrict__ x,
                                                   const float* __restrict__ w)
{
    __shared__ float As[BK][BM + 4];   // [k][row], +4 keeps 16B alignment & kills conflicts
    __shared__ float Ws[BK][BN + 4];   // [k][col]

    const int tid = threadIdx.x;
    const int tx  = tid & 15;   // column group: cols tx*8 .. tx*8+7
    const int ty  = tid >> 4;   // row group:    rows ty*8 .. ty*8+7
    const int blockRow = blockIdx.x * BM;

    float acc[TM][TN];
    #pragma unroll
    for (int i = 0; i < TM; i++)
        #pragma unroll
        for (int j = 0; j < TN; j++) acc[i][j] = 0.f;

    for (int kt = 0; kt < D_IN; kt += BK) {
        // A tile: 128 rows x 16 k (2048 elems, 8 per thread)
        #pragma unroll
        for (int i = 0; i < (BM * BK) / 256; i++) {
            int e = i * 256 + tid;
            int r = e >> 4;
            int k = e & 15;
            int row = blockRow + r;
            As[k][r] = (row < N_NODES) ? x[row * D_IN + kt + k] : 0.f;
        }
        // W tile: 128 cols x 16 k (2048 elems, 8 per thread)
        #pragma unroll
        for (int i = 0; i < (BN * BK) / 256; i++) {
            int e = i * 256 + tid;
            int c = e >> 4;
            int k = e & 15;
            Ws[k][c] = w[c * D_IN + kt + k];
        }
        __syncthreads();

        #pragma unroll
        for (int kk = 0; kk < BK; kk++) {
            float a[TM], b[TN];
            // two LDS.128 each (addresses 16B-aligned: ty*8, tx*8 element offsets)
            #pragma unroll
            for (int i = 0; i < TM; i++) a[i] = As[kk][ty * TM + i];
            #pragma unroll
            for (int j = 0; j < TN; j++) b[j] = Ws[kk][tx * TN + j];
            #pragma unroll
            for (int i = 0; i < TM; i++)
                #pragma unroll
                for (int j = 0; j < TN; j++)
                    acc[i][j] = fmaf(a[i], b[j], acc[i][j]);
        }
        __syncthreads();
    }

    #pragma unroll
    for (int i = 0; i < TM; i++) {
        int row = blockRow + ty * TM + i;
        if (row < N_NODES) {
            float4 v0 = make_float4(acc[i][0], acc[i][1], acc[i][2], acc[i][3]);
            float4 v1 = make_float4(acc[i][4], acc[i][5], acc[i][6], acc[i][7]);
            float4* p = reinterpret_cast<float4*>(&g_seq[row * D_OUT + tx * TN]);
            p[0] = v0;
            p[1] = v1;
        }
    }
}

// ---------------------------------------------------------------------------
// Kernel 2: out[n][o] = bias[o]   (out is poisoned before timing) — float4
// ---------------------------------------------------------------------------
__global__ void init_kernel(float4* __restrict__ out, const float4* __restrict__ bias)
{
    int i = blockIdx.x * blockDim.x + threadIdx.x;
    if (i < (N_NODES * D_OUT) / 4) out[i] = bias[i & 31];   // 128 floats = 32 float4
}

// ---------------------------------------------------------------------------
// Kernel 3: scatter-add.  One warp per edge; lane j handles 4 consecutive
// output features: one float4 load of seq[col] + ONE red.global.add.v4.f32.
// 4x fewer L2 atomic ops than scalar atomicAdd.
// ---------------------------------------------------------------------------
__global__ __launch_bounds__(256) void scatter_kernel(const float* __restrict__ ev,
                                                      const int*   __restrict__ er,
                                                      const int*   __restrict__ ec,
                                                      float*       __restrict__ out)
{
    long long idx = (long long)blockIdx.x * blockDim.x + threadIdx.x;
    int e    = (int)(idx >> 5);
    int lane = (int)(idx & 31);
    if (e >= N_EDGES) return;

    int   row = er[e];
    int   col = ec[e];
    float v   = ev[e];

    const float4 s = reinterpret_cast<const float4*>(g_seq)[col * 32 + lane];
    float* o = out + (long long)row * D_OUT + lane * 4;
    asm volatile("red.global.add.v4.f32 [%0], {%1, %2, %3, %4};"
                 :: "l"(o), "f"(v * s.x), "f"(v * s.y), "f"(v * s.z), "f"(v * s.w)
                 : "memory");
}

// ---------------------------------------------------------------------------
// Kernel 4: PReLU in place (single shared slope alpha[0]).
// ---------------------------------------------------------------------------
__global__ void prelu_kernel(float* __restrict__ out, const float* __restrict__ alpha)
{
    int i = blockIdx.x * blockDim.x + threadIdx.x;
    if (i >= (N_NODES * D_OUT) / 4) return;
    float a = alpha[0];
    float4 v = reinterpret_cast<float4*>(out)[i];
    v.x = v.x > 0.f ? v.x : a * v.x;
    v.y = v.y > 0.f ? v.y : a * v.y;
    v.z = v.z > 0.f ? v.z : a * v.z;
    v.w = v.w > 0.f ? v.w : a * v.w;
    reinterpret_cast<float4*>(out)[i] = v;
}

// ---------------------------------------------------------------------------
// Launch. Input order (metadata): x, weight, bias, alpha, edge_val, edge_row,
// edge_col. Output: fp32 [40000*128].
// ---------------------------------------------------------------------------
extern "C" void kernel_launch(void* const* d_in, const int* in_sizes, int n_in,
                              void* d_out, int out_size)
{
    const float* x     = (const float*)d_in[0];
    const float* w     = (const float*)d_in[1];
    const float* bias  = (const float*)d_in[2];
    const float* alpha = (const float*)d_in[3];
    const float* ev    = (const float*)d_in[4];
    const int*   er    = (const int*)  d_in[5];
    const int*   ec    = (const int*)  d_in[6];
    float*       out   = (float*)d_out;

    // 1) GEMM: ceil(40000/128) = 313 blocks
    gemm_kernel<<<(N_NODES + BM - 1) / BM, 256>>>(x, w);

    // 2) out = bias
    {
        int n4 = (N_NODES * D_OUT) / 4;
        init_kernel<<<(n4 + 255) / 256, 256>>>((float4*)out, (const float4*)bias);
    }

    // 3) scatter-add: 640000 edges * 32 lanes
    {
        long long threads = (long long)N_EDGES * 32;
        int blocks = (int)((threads + 255) / 256);
        scatter_kernel<<<blocks, 256>>>(ev, er, ec, out);
    }

    // 4) PReLU
    {
        int n4 = (N_NODES * D_OUT) / 4;
        prelu_kernel<<<(n4 + 255) / 256, 256>>>(out, alpha);
    }
}